// round 12
// baseline (speedup 1.0000x reference)
#include <cuda_runtime.h>
#include <cuda_bf16.h>
#include <stdint.h>
#include <math.h>

// Problem constants
static const int cB = 8;
static const int cS = 2048;
static const int cD = 512;
static const int cL = 6;
static const int cF = 2048;   // 4*D
static const int cM = cB * cS; // 16384 rows

// ---------------------------------------------------------------------------
// Scratch (static device allocations)
// ---------------------------------------------------------------------------
__device__ float g_x  [cM * cD];
__device__ float g_ao [cM * cD];                  // also reused as fp32 q staging
__device__ float g_att[(long long)cB * cS * cS];  // also reused as fp32 k staging + h staging
__device__ float g_tab[cL * cS];

__device__ __nv_bfloat16 g_vh [cM * cD], g_vl [cM * cD];
__device__ __nv_bfloat16 g_ph [(long long)cB * cS * cS], g_pl[(long long)cB * cS * cS];

// int8 limb arrays + per-row scales
__device__ int8_t g_xn1[cM * cD], g_xn0[cM * cD];
__device__ int8_t g_q1 [cM * cD], g_q0 [cM * cD];
__device__ int8_t g_k1 [cM * cD], g_k0 [cM * cD];
__device__ int8_t g_h1 [(long long)cM * cF], g_h0 [(long long)cM * cF];
__device__ int8_t g_wq1[cL * cD * cD], g_wq0[cL * cD * cD];
__device__ int8_t g_wk1[cL * cD * cD], g_wk0[cL * cD * cD];
__device__ int8_t g_wv1[cL * cD * cD], g_wv0[cL * cD * cD];
__device__ int8_t g_f11[cL * cF * cD], g_f10[cL * cF * cD];
__device__ int8_t g_f21[cL * cD * cF], g_f20[cL * cD * cF];
__device__ float g_xns[cM], g_qs[cM], g_ks[cM], g_hs[cM];
__device__ float g_wqs[cL * cD], g_wks[cL * cD], g_wvs[cL * cD];
__device__ float g_f1s[cL * cF], g_f2s[cL * cD];

// ---------------------------------------------------------------------------
// PTX helpers (sm_80-level, portable)
// ---------------------------------------------------------------------------
__device__ __forceinline__ uint32_t smem_to_u32(const void* p) {
    uint32_t a;
    asm("{ .reg .u64 t; cvta.to.shared.u64 t, %1; cvt.u32.u64 %0, t; }" : "=r"(a) : "l"(p));
    return a;
}
__device__ __forceinline__ void cp_async16(uint32_t saddr, const void* gaddr) {
    asm volatile("cp.async.cg.shared.global [%0], [%1], 16;" :: "r"(saddr), "l"(gaddr));
}
__device__ __forceinline__ void cp_commit() { asm volatile("cp.async.commit_group;"); }
template<int N>
__device__ __forceinline__ void cp_wait() { asm volatile("cp.async.wait_group %0;" :: "n"(N)); }
__device__ __forceinline__ void ldsm4(uint32_t* r, uint32_t addr) {
    asm volatile("ldmatrix.sync.aligned.m8n8.x4.shared.b16 {%0,%1,%2,%3}, [%4];"
        : "=r"(r[0]), "=r"(r[1]), "=r"(r[2]), "=r"(r[3]) : "r"(addr));
}
__device__ __forceinline__ void ldsm4t(uint32_t* r, uint32_t addr) {
    asm volatile("ldmatrix.sync.aligned.m8n8.x4.trans.shared.b16 {%0,%1,%2,%3}, [%4];"
        : "=r"(r[0]), "=r"(r[1]), "=r"(r[2]), "=r"(r[3]) : "r"(addr));
}
__device__ __forceinline__ void mma16816(float* c, const uint32_t* a, uint32_t b0, uint32_t b1) {
    asm volatile(
        "mma.sync.aligned.m16n8k16.row.col.f32.bf16.bf16.f32 "
        "{%0,%1,%2,%3}, {%4,%5,%6,%7}, {%8,%9}, {%0,%1,%2,%3};"
        : "+f"(c[0]), "+f"(c[1]), "+f"(c[2]), "+f"(c[3])
        : "r"(a[0]), "r"(a[1]), "r"(a[2]), "r"(a[3]), "r"(b0), "r"(b1));
}
__device__ __forceinline__ void mma_s8(int* c, const uint32_t* a, uint32_t b0, uint32_t b1) {
    asm volatile(
        "mma.sync.aligned.m16n8k32.row.col.s32.s8.s8.s32 "
        "{%0,%1,%2,%3}, {%4,%5,%6,%7}, {%8,%9}, {%0,%1,%2,%3};"
        : "+r"(c[0]), "+r"(c[1]), "+r"(c[2]), "+r"(c[3])
        : "r"(a[0]), "r"(a[1]), "r"(a[2]), "r"(a[3]), "r"(b0), "r"(b1));
}

// quantize one value given invs (= 16256/max): returns limbs
__device__ __forceinline__ void quant1(float x, float invs, int& h1, int& h0) {
    float t = x * invs;
    h1 = __float2int_rn(t * 0.0078125f);   // /128
    h0 = __float2int_rn(t - 128.0f * (float)h1);
}

// ---------------------------------------------------------------------------
// Encoder
// ---------------------------------------------------------------------------
__global__ void enc_kernel(const float* __restrict__ z, const float* __restrict__ c,
                           const float* __restrict__ ew, const float* __restrict__ eb,
                           float* __restrict__ x)
{
    long long idx = (long long)blockIdx.x * blockDim.x + threadIdx.x;
    if (idx >= (long long)cM * cD) return;
    int d = (int)(idx & (cD - 1));
    long long bs = idx >> 9;
    int s = (int)(bs & (cS - 1));
    const float factor = -1.7988946039015984e-2f;
    float div = expf((float)(2 * (d >> 1)) * factor);
    float ang = (float)s * div;
    float pe = (d & 1) ? cosf(ang) : sinf(ang);
    x[idx] = z[bs] * ew[2 * d] + c[bs] * ew[2 * d + 1] + eb[d] + pe;
}

__global__ void btab_all(const float* __restrict__ beta, float* __restrict__ tab)
{
    int i = blockIdx.x * blockDim.x + threadIdx.x;
    if (i < cL * cS) {
        int l = i / cS, t = i - l * cS;
        const float TWO_PI = 6.283185307179586476925f;
        tab[i] = beta[2 * l] * cosf(TWO_PI * (float)t / 24.0f)
               + beta[2 * l + 1] * cosf(TWO_PI * (float)t / 720.0f);
    }
}

// ---------------------------------------------------------------------------
// Per-row int8 2-limb quantization body (row cached in smem)
// ---------------------------------------------------------------------------
__device__ void rowquant_body(const float* __restrict__ src, int8_t* __restrict__ d1,
                              int8_t* __restrict__ d0, float* __restrict__ scale,
                              long long row, int len)
{
    __shared__ float rbuf[2048];
    __shared__ float red[8];
    const float* s = src + row * len;
    int tid = threadIdx.x;
    float mx = 0.0f;
    for (int j = tid * 4; j < len; j += 1024) {
        float4 v = *(const float4*)(s + j);
        *(float4*)(rbuf + j) = v;
        mx = fmaxf(mx, fmaxf(fmaxf(fabsf(v.x), fabsf(v.y)), fmaxf(fabsf(v.z), fabsf(v.w))));
    }
    #pragma unroll
    for (int o = 16; o; o >>= 1) mx = fmaxf(mx, __shfl_xor_sync(0xffffffffu, mx, o));
    if ((tid & 31) == 0) red[tid >> 5] = mx;
    __syncthreads();
    float m = red[0];
    #pragma unroll
    for (int w = 1; w < 8; w++) m = fmaxf(m, red[w]);
    m = fmaxf(m, 1e-30f);
    float invs = 16256.0f / m;
    if (tid == 0) scale[row] = m / 16256.0f;
    for (int j = tid * 4; j < len; j += 1024) {
        float4 v = *(const float4*)(rbuf + j);
        int a1, a0, b1, b0, c1, c0, e1, e0;
        quant1(v.x, invs, a1, a0);
        quant1(v.y, invs, b1, b0);
        quant1(v.z, invs, c1, c0);
        quant1(v.w, invs, e1, e0);
        *(char4*)(d1 + row * len + j) = make_char4((char)a1, (char)b1, (char)c1, (char)e1);
        *(char4*)(d0 + row * len + j) = make_char4((char)a0, (char)b0, (char)c0, (char)e0);
    }
}

__global__ __launch_bounds__(256) void rowquant_kernel(
    const float* __restrict__ src, int8_t* __restrict__ d1, int8_t* __restrict__ d0,
    float* __restrict__ scale, int len)
{
    rowquant_body(src, d1, d0, scale, blockIdx.x, len);
}

// All weight tensors, one launch. Row regions: wq|wk|wv|f1|f2
__global__ __launch_bounds__(256) void wquant_all(
    const float* wq, const float* wk, const float* wv, const float* f1, const float* f2,
    int8_t* wq1, int8_t* wq0, int8_t* wk1, int8_t* wk0, int8_t* wv1, int8_t* wv0,
    int8_t* f11, int8_t* f10, int8_t* f21, int8_t* f20,
    float* wqs, float* wks, float* wvs, float* f1s, float* f2s)
{
    int r = blockIdx.x;
    const int nQ = cL * cD;        // 3072 rows each for wq/wk/wv
    const int nF1 = cL * cF;       // 12288 rows for f1
    if (r < nQ)                 rowquant_body(wq, wq1, wq0, wqs, r, cD);
    else if (r < 2 * nQ)        rowquant_body(wk, wk1, wk0, wks, r - nQ, cD);
    else if (r < 3 * nQ)        rowquant_body(wv, wv1, wv0, wvs, r - 2 * nQ, cD);
    else if (r < 3 * nQ + nF1)  rowquant_body(f1, f11, f10, f1s, r - 3 * nQ, cD);
    else                        rowquant_body(f2, f21, f20, f2s, r - 3 * nQ - nF1, cF);
}

// ---------------------------------------------------------------------------
// LayerNorm (fp32 out) — residual variant
// ---------------------------------------------------------------------------
__global__ __launch_bounds__(128) void ln_kernel(
    const float* __restrict__ x, const float* __restrict__ res,
    const float* __restrict__ w, const float* __restrict__ b,
    float* __restrict__ out)
{
    long long off = (long long)blockIdx.x * cD + threadIdx.x * 4;
    float4 v = *(const float4*)(x + off);
    if (res) {
        float4 r = *(const float4*)(res + off);
        v.x += r.x; v.y += r.y; v.z += r.z; v.w += r.w;
    }
    int lane = threadIdx.x & 31, warp = threadIdx.x >> 5;
    __shared__ float red1[4];
    __shared__ float red2[4];
    float s = v.x + v.y + v.z + v.w;
    #pragma unroll
    for (int o = 16; o; o >>= 1) s += __shfl_xor_sync(0xffffffffu, s, o);
    if (lane == 0) red1[warp] = s;
    __syncthreads();
    float mean = (red1[0] + red1[1] + red1[2] + red1[3]) * (1.0f / 512.0f);
    float d0 = v.x - mean, d1 = v.y - mean, d2 = v.z - mean, d3 = v.w - mean;
    float q = d0 * d0 + d1 * d1 + d2 * d2 + d3 * d3;
    #pragma unroll
    for (int o = 16; o; o >>= 1) q += __shfl_xor_sync(0xffffffffu, q, o);
    if (lane == 0) red2[warp] = q;
    __syncthreads();
    float var = (red2[0] + red2[1] + red2[2] + red2[3]) * (1.0f / 512.0f);
    float rs = rsqrtf(var + 1e-5f);
    float4 wv = *(const float4*)(w + threadIdx.x * 4);
    float4 bv = *(const float4*)(b + threadIdx.x * 4);
    float4 o4;
    o4.x = d0 * rs * wv.x + bv.x;
    o4.y = d1 * rs * wv.y + bv.y;
    o4.z = d2 * rs * wv.z + bv.z;
    o4.w = d3 * rs * wv.w + bv.w;
    *(float4*)(out + off) = o4;
}

// LayerNorm producing int8 limbs + per-row scale
__global__ __launch_bounds__(128) void ln_q_kernel(
    const float* __restrict__ x,
    const float* __restrict__ w, const float* __restrict__ b,
    int8_t* __restrict__ d1, int8_t* __restrict__ d0, float* __restrict__ scale)
{
    long long off = (long long)blockIdx.x * cD + threadIdx.x * 4;
    float4 v = *(const float4*)(x + off);
    int lane = threadIdx.x & 31, warp = threadIdx.x >> 5;
    __shared__ float red1[4];
    __shared__ float red2[4];
    __shared__ float red3[4];
    float s = v.x + v.y + v.z + v.w;
    #pragma unroll
    for (int o = 16; o; o >>= 1) s += __shfl_xor_sync(0xffffffffu, s, o);
    if (lane == 0) red1[warp] = s;
    __syncthreads();
    float mean = (red1[0] + red1[1] + red1[2] + red1[3]) * (1.0f / 512.0f);
    float e0 = v.x - mean, e1 = v.y - mean, e2 = v.z - mean, e3 = v.w - mean;
    float q = e0 * e0 + e1 * e1 + e2 * e2 + e3 * e3;
    #pragma unroll
    for (int o = 16; o; o >>= 1) q += __shfl_xor_sync(0xffffffffu, q, o);
    if (lane == 0) red2[warp] = q;
    __syncthreads();
    float var = (red2[0] + red2[1] + red2[2] + red2[3]) * (1.0f / 512.0f);
    float rs = rsqrtf(var + 1e-5f);
    float4 wv = *(const float4*)(w + threadIdx.x * 4);
    float4 bv = *(const float4*)(b + threadIdx.x * 4);
    float o4[4];
    o4[0] = e0 * rs * wv.x + bv.x;
    o4[1] = e1 * rs * wv.y + bv.y;
    o4[2] = e2 * rs * wv.z + bv.z;
    o4[3] = e3 * rs * wv.w + bv.w;
    float mx = fmaxf(fmaxf(fabsf(o4[0]), fabsf(o4[1])), fmaxf(fabsf(o4[2]), fabsf(o4[3])));
    #pragma unroll
    for (int o = 16; o; o >>= 1) mx = fmaxf(mx, __shfl_xor_sync(0xffffffffu, mx, o));
    if (lane == 0) red3[warp] = mx;
    __syncthreads();
    float m = fmaxf(fmaxf(red3[0], red3[1]), fmaxf(red3[2], red3[3]));
    m = fmaxf(m, 1e-30f);
    float invs = 16256.0f / m;
    if (threadIdx.x == 0) scale[blockIdx.x] = m / 16256.0f;
    int a1, a0, b1, b0, c1, c0, f1, f0;
    quant1(o4[0], invs, a1, a0);
    quant1(o4[1], invs, b1, b0);
    quant1(o4[2], invs, c1, c0);
    quant1(o4[3], invs, f1, f0);
    *(char4*)(d1 + off) = make_char4((char)a1, (char)b1, (char)c1, (char)f1);
    *(char4*)(d0 + off) = make_char4((char)a0, (char)b0, (char)c0, (char)f0);
}

// ---------------------------------------------------------------------------
// Softmax with distance bias: fp32 logits in, hi/lo bf16 probs out
// ---------------------------------------------------------------------------
__global__ __launch_bounds__(256) void softmax_kernel(
    const float* __restrict__ att, const float* __restrict__ tab,
    __nv_bfloat16* __restrict__ ph, __nv_bfloat16* __restrict__ pl)
{
    __shared__ float buf[cS];
    __shared__ float red[8];
    int i = blockIdx.x, b = blockIdx.y;
    long long roff = ((long long)b * cS + i) * cS;
    const float* row = att + roff;
    int tid = threadIdx.x;
    float mx = -3.4e38f;
    for (int j = tid; j < cS; j += 256) {
        int d = i - j; if (d < 0) d = -d;
        float vv = row[j] + tab[d];
        buf[j] = vv;
        mx = fmaxf(mx, vv);
    }
    #pragma unroll
    for (int o = 16; o; o >>= 1) mx = fmaxf(mx, __shfl_xor_sync(0xffffffffu, mx, o));
    if ((tid & 31) == 0) red[tid >> 5] = mx;
    __syncthreads();
    float m = red[0];
    #pragma unroll
    for (int w2 = 1; w2 < 8; w2++) m = fmaxf(m, red[w2]);
    __syncthreads();
    float sum = 0.0f;
    for (int j = tid; j < cS; j += 256) {
        float e = expf(buf[j] - m);
        buf[j] = e;
        sum += e;
    }
    #pragma unroll
    for (int o = 16; o; o >>= 1) sum += __shfl_xor_sync(0xffffffffu, sum, o);
    if ((tid & 31) == 0) red[tid >> 5] = sum;
    __syncthreads();
    float tot = 0.0f;
    #pragma unroll
    for (int w2 = 0; w2 < 8; w2++) tot += red[w2];
    float inv = 1.0f / tot;
    for (int j = tid; j < cS; j += 256) {
        float p = buf[j] * inv;
        __nv_bfloat16 hv = __float2bfloat16(p);
        ph[roff + j] = hv;
        pl[roff + j] = __float2bfloat16(p - __bfloat162float(hv));
    }
}

// ---------------------------------------------------------------------------
// INT8 2-limb GEMM: C = alpha * sa[r]*sb[c] * ((A1,A0) @ (B1,B0)^T) (+bias)(+src)(relu)
//   A limbs [M,K] K-major, B limbs [N,K] K-major. CTA 128x128x32, 8 warps.
//   3 limb products: S11 (acc hi), S10+S01 (acc mid); value = 16384*S11 + 128*Smid.
// ---------------------------------------------------------------------------
static const int QROW = 48;                    // bytes per smem row (32 data + 16 pad)
static const int QTILE = 128 * QROW;           // 6144
static const int Q_A1 = 0;
static const int Q_A0 = 2 * QTILE;
static const int Q_B1 = 4 * QTILE;
static const int Q_B0 = 6 * QTILE;
static const int Q_SMEM = 8 * QTILE;           // 49152

template<bool OUTF32, bool OUTHL, bool RELU, bool ADDSRC>
__global__ __launch_bounds__(256, 1) void qgemm(
    const int8_t* __restrict__ A1, const int8_t* __restrict__ A0,
    const int8_t* __restrict__ B1, const int8_t* __restrict__ B0,
    const float* __restrict__ sa, const float* __restrict__ sbv_,
    const float* __restrict__ bias, const float* __restrict__ src,
    float* __restrict__ C, __nv_bfloat16* __restrict__ Ch, __nv_bfloat16* __restrict__ Cl,
    int N, int K, long long bsA, long long bsB, long long bsC,
    long long bsSA, long long bsSB, float alpha)
{
    extern __shared__ __align__(16) char smem[];
    const uint32_t smb = smem_to_u32(smem);
    const int tid = threadIdx.x;
    const int wid = tid >> 5, lane = tid & 31;

    A1 += (long long)blockIdx.z * bsA;  A0 += (long long)blockIdx.z * bsA;
    B1 += (long long)blockIdx.z * bsB;  B0 += (long long)blockIdx.z * bsB;
    sa += (long long)blockIdx.z * bsSA;
    sbv_ += (long long)blockIdx.z * bsSB;
    const long long zC = (long long)blockIdx.z * bsC;

    const int rowBase = blockIdx.y * 128;
    const int colBase = blockIdx.x * 128;

    // loader: thread t -> row t>>1, 16B half (t&1)
    const int ldRow = tid >> 1;
    const int ldHalf = (tid & 1) << 4;
    const long long gA = (long long)(rowBase + ldRow) * K + ldHalf;
    const long long gB = (long long)(colBase + ldRow) * K + ldHalf;
    const uint32_t sOff = (uint32_t)(ldRow * QROW + ldHalf);

    const int nkt = K >> 5;

    // prologue
    {
        cp_async16(smb + Q_A1 + sOff, A1 + gA);
        cp_async16(smb + Q_A0 + sOff, A0 + gA);
        cp_async16(smb + Q_B1 + sOff, B1 + gB);
        cp_async16(smb + Q_B0 + sOff, B0 + gB);
        cp_commit();
    }

    const int wm = wid >> 1, wn = wid & 1;
    const int lq = lane >> 3, lr = lane & 7;
    const int lrow = lr + (lq & 1) * 8;
    const int lcolB = (lq >> 1) * 16;     // byte offset 0/16 (8 b16 cols)
    const uint32_t aBase = (uint32_t)((wm * 32 + lrow) * QROW + lcolB);
    const uint32_t bBase = (uint32_t)((wn * 64 + lrow) * QROW + lcolB);

    int accH[16][4], accM[16][4];
    #pragma unroll
    for (int i = 0; i < 16; i++)
        #pragma unroll
        for (int j = 0; j < 4; j++) { accH[i][j] = 0; accM[i][j] = 0; }

    for (int kt = 0; kt < nkt; kt++) {
        const int buf = kt & 1;
        if (kt + 1 < nkt) {
            const uint32_t bo = (uint32_t)((kt + 1) & 1) * QTILE;
            const long long a0 = gA + (long long)(kt + 1) * 32;
            const long long b0 = gB + (long long)(kt + 1) * 32;
            cp_async16(smb + Q_A1 + bo + sOff, A1 + a0);
            cp_async16(smb + Q_A0 + bo + sOff, A0 + a0);
            cp_async16(smb + Q_B1 + bo + sOff, B1 + b0);
            cp_async16(smb + Q_B0 + bo + sOff, B0 + b0);
            cp_commit();
            cp_wait<1>();
        } else {
            cp_wait<0>();
        }
        __syncthreads();

        const uint32_t a1p = smb + Q_A1 + (uint32_t)buf * QTILE + aBase;
        const uint32_t a0p = smb + Q_A0 + (uint32_t)buf * QTILE + aBase;
        const uint32_t b1p = smb + Q_B1 + (uint32_t)buf * QTILE + bBase;
        const uint32_t b0p = smb + Q_B0 + (uint32_t)buf * QTILE + bBase;

        uint32_t a1f[2][4], a0f[2][4];
        ldsm4(a1f[0], a1p);
        ldsm4(a1f[1], a1p + 16 * QROW);
        ldsm4(a0f[0], a0p);
        ldsm4(a0f[1], a0p + 16 * QROW);

        #pragma unroll
        for (int np = 0; np < 4; np++) {
            uint32_t b1f[4], b0f[4];
            ldsm4(b1f, b1p + np * 16 * QROW);
            ldsm4(b0f, b0p + np * 16 * QROW);
            #pragma unroll
            for (int mi = 0; mi < 2; mi++)
                #pragma unroll
                for (int nt = 0; nt < 2; nt++)
                    mma_s8(accH[mi * 8 + np * 2 + nt], a1f[mi], b1f[nt], b1f[nt + 2]);
            #pragma unroll
            for (int mi = 0; mi < 2; mi++)
                #pragma unroll
                for (int nt = 0; nt < 2; nt++)
                    mma_s8(accM[mi * 8 + np * 2 + nt], a1f[mi], b0f[nt], b0f[nt + 2]);
            #pragma unroll
            for (int mi = 0; mi < 2; mi++)
                #pragma unroll
                for (int nt = 0; nt < 2; nt++)
                    mma_s8(accM[mi * 8 + np * 2 + nt], a0f[mi], b1f[nt], b1f[nt + 2]);
        }
        __syncthreads();
    }

    // Epilogue
    const int eg = lane >> 2, et = (lane & 3) * 2;
    float sav[2][2];
    #pragma unroll
    for (int mi = 0; mi < 2; mi++)
        #pragma unroll
        for (int hf = 0; hf < 2; hf++)
            sav[mi][hf] = sa[rowBase + wm * 32 + mi * 16 + eg + hf * 8] * alpha;

    #pragma unroll
    for (int mi = 0; mi < 2; mi++) {
        #pragma unroll
        for (int np = 0; np < 4; np++) {
            #pragma unroll
            for (int nt = 0; nt < 2; nt++) {
                const int f = mi * 8 + np * 2 + nt;
                const int col = colBase + wn * 64 + np * 16 + nt * 8 + et;
                const float sb0 = sbv_[col], sb1 = sbv_[col + 1];
                #pragma unroll
                for (int hf = 0; hf < 2; hf++) {
                    const long long r = rowBase + wm * 32 + mi * 16 + eg + hf * 8;
                    float comb0 = 16384.0f * (float)accH[f][hf * 2]     + 128.0f * (float)accM[f][hf * 2];
                    float comb1 = 16384.0f * (float)accH[f][hf * 2 + 1] + 128.0f * (float)accM[f][hf * 2 + 1];
                    float v0 = sav[mi][hf] * sb0 * comb0;
                    float v1 = sav[mi][hf] * sb1 * comb1;
                    if (bias) { v0 += bias[col]; v1 += bias[col + 1]; }
                    if (ADDSRC) {
                        float2 sv = *(const float2*)(src + zC + r * (long long)N + col);
                        v0 += sv.x; v1 += sv.y;
                    }
                    if (RELU) { v0 = fmaxf(v0, 0.0f); v1 = fmaxf(v1, 0.0f); }
                    if (OUTF32) {
                        float2 o; o.x = v0; o.y = v1;
                        *(float2*)(C + zC + r * (long long)N + col) = o;
                    }
                    if (OUTHL) {
                        __nv_bfloat16 h0 = __float2bfloat16(v0);
                        __nv_bfloat16 h1 = __float2bfloat16(v1);
                        __nv_bfloat16 l0 = __float2bfloat16(v0 - __bfloat162float(h0));
                        __nv_bfloat16 l1 = __float2bfloat16(v1 - __bfloat162float(h1));
                        __nv_bfloat16 hp[2] = {h0, h1};
                        __nv_bfloat16 lp[2] = {l0, l1};
                        *(uint32_t*)(Ch + zC + r * (long long)N + col) = *(uint32_t*)hp;
                        *(uint32_t*)(Cl + zC + r * (long long)N + col) = *(uint32_t*)lp;
                    }
                }
            }
        }
    }
}

// ---------------------------------------------------------------------------
// bf16 3-term GEMM, NN variant only (P @ V): A [M,K] K-major hi/lo,
// B [K,N] row-major hi/lo via ldmatrix.trans. (validated in R10)
// ---------------------------------------------------------------------------
static const int TPAD = 40;
static const int TPADN = 136;
static const int TILE_BYTES = 128 * TPAD * 2;
static const int O_AH = 0;
static const int O_AL = O_AH + 2 * TILE_BYTES;
static const int O_BH = O_AL + 2 * TILE_BYTES;
static const int O_BL = O_BH + 2 * TILE_BYTES;
static const int T_SMEM = O_BL + 2 * TILE_BYTES;

__global__ __launch_bounds__(256, 2) void tgemm_nn(
    const __nv_bfloat16* __restrict__ Ah, const __nv_bfloat16* __restrict__ Al,
    const __nv_bfloat16* __restrict__ Bh, const __nv_bfloat16* __restrict__ Bl,
    float* __restrict__ C, int N, int K,
    long long bsA, long long bsB, long long bsC)
{
    extern __shared__ __align__(16) char smem[];
    const uint32_t sb = smem_to_u32(smem);
    const int tid = threadIdx.x;
    const int wid = tid >> 5, lane = tid & 31;

    Ah += (long long)blockIdx.z * bsA;  Al += (long long)blockIdx.z * bsA;
    Bh += (long long)blockIdx.z * bsB;  Bl += (long long)blockIdx.z * bsB;
    const long long zC = (long long)blockIdx.z * bsC;

    const int rowBase = blockIdx.y * 128;
    const int colBase = blockIdx.x * 128;

    const int ldRow = tid >> 1;
    const int ldOff = (tid & 1) << 4;
    const long long gA = (long long)(rowBase + ldRow) * K + ldOff;
    const uint32_t sOffA = (uint32_t)(ldRow * TPAD + ldOff) * 2;

    const int nr0 = tid >> 4,         nc0 = tid & 15;
    const int nr1 = (tid + 256) >> 4, nc1 = tid & 15;
    const uint32_t sB0 = (uint32_t)(nr0 * TPADN + nc0 * 8) * 2;
    const uint32_t sB1 = (uint32_t)(nr1 * TPADN + nc1 * 8) * 2;
    const long long gBn0 = (long long)nr0 * N + colBase + nc0 * 8;
    const long long gBn1 = (long long)nr1 * N + colBase + nc1 * 8;

    const int nkt = K >> 5;
    {
        cp_async16(sb + O_AH + sOffA,      Ah + gA);
        cp_async16(sb + O_AH + sOffA + 16, Ah + gA + 8);
        cp_async16(sb + O_AL + sOffA,      Al + gA);
        cp_async16(sb + O_AL + sOffA + 16, Al + gA + 8);
        cp_async16(sb + O_BH + sB0, Bh + gBn0);
        cp_async16(sb + O_BH + sB1, Bh + gBn1);
        cp_async16(sb + O_BL + sB0, Bl + gBn0);
        cp_async16(sb + O_BL + sB1, Bl + gBn1);
        cp_commit();
    }

    const int wm = wid >> 1, wn = wid & 1;
    const int lq = lane >> 3, lr = lane & 7;
    const int lrow = lr + (lq & 1) * 8;
    const int lcol = (lq >> 1) * 8;
    const uint32_t aBase  = (uint32_t)((wm * 32 + lrow) * TPAD + lcol) * 2;
    const uint32_t bBaseN = (uint32_t)(lrow * TPADN + wn * 64 + lcol) * 2;

    float acc[16][4];
    #pragma unroll
    for (int i = 0; i < 16; i++)
        #pragma unroll
        for (int j = 0; j < 4; j++) acc[i][j] = 0.0f;

    for (int kt = 0; kt < nkt; kt++) {
        const int buf = kt & 1;
        if (kt + 1 < nkt) {
            const uint32_t bo = (uint32_t)((kt + 1) & 1) * TILE_BYTES;
            const long long a0 = gA + (long long)(kt + 1) * 32;
            cp_async16(sb + O_AH + bo + sOffA,      Ah + a0);
            cp_async16(sb + O_AH + bo + sOffA + 16, Ah + a0 + 8);
            cp_async16(sb + O_AL + bo + sOffA,      Al + a0);
            cp_async16(sb + O_AL + bo + sOffA + 16, Al + a0 + 8);
            const long long b0 = (long long)(kt + 1) * 32 * N;
            cp_async16(sb + O_BH + bo + sB0, Bh + b0 + gBn0);
            cp_async16(sb + O_BH + bo + sB1, Bh + b0 + gBn1);
            cp_async16(sb + O_BL + bo + sB0, Bl + b0 + gBn0);
            cp_async16(sb + O_BL + bo + sB1, Bl + b0 + gBn1);
            cp_commit();
            cp_wait<1>();
        } else {
            cp_wait<0>();
        }
        __syncthreads();

        const uint32_t ah0 = sb + O_AH + (uint32_t)buf * TILE_BYTES + aBase;
        const uint32_t al0 = sb + O_AL + (uint32_t)buf * TILE_BYTES + aBase;
        const uint32_t bh0 = sb + O_BH + (uint32_t)buf * TILE_BYTES + bBaseN;
        const uint32_t bl0 = sb + O_BL + (uint32_t)buf * TILE_BYTES + bBaseN;

        #pragma unroll
        for (int ks = 0; ks < 2; ks++) {
            uint32_t ah[2][4], al[2][4];
            ldsm4(ah[0], ah0 + ks * 32);
            ldsm4(ah[1], ah0 + 16 * TPAD * 2 + ks * 32);
            ldsm4(al[0], al0 + ks * 32);
            ldsm4(al[1], al0 + 16 * TPAD * 2 + ks * 32);
            #pragma unroll
            for (int np = 0; np < 4; np++) {
                uint32_t bh[4], bl[4];
                const uint32_t o = (uint32_t)(ks * 16 * TPADN * 2 + np * 32);
                ldsm4t(bh, bh0 + o);
                ldsm4t(bl, bl0 + o);
                #pragma unroll
                for (int mi = 0; mi < 2; mi++)
                    #pragma unroll
                    for (int nt = 0; nt < 2; nt++)
                        mma16816(acc[mi * 8 + np * 2 + nt], ah[mi], bh[nt * 2], bh[nt * 2 + 1]);
                #pragma unroll
                for (int mi = 0; mi < 2; mi++)
                    #pragma unroll
                    for (int nt = 0; nt < 2; nt++)
                        mma16816(acc[mi * 8 + np * 2 + nt], ah[mi], bl[nt * 2], bl[nt * 2 + 1]);
                #pragma unroll
                for (int mi = 0; mi < 2; mi++)
                    #pragma unroll
                    for (int nt = 0; nt < 2; nt++)
                        mma16816(acc[mi * 8 + np * 2 + nt], al[mi], bh[nt * 2], bh[nt * 2 + 1]);
            }
        }
        __syncthreads();
    }

    const int eg = lane >> 2, et = (lane & 3) * 2;
    #pragma unroll
    for (int mi = 0; mi < 2; mi++)
        #pragma unroll
        for (int np = 0; np < 4; np++)
            #pragma unroll
            for (int nt = 0; nt < 2; nt++) {
                const float* cf = acc[mi * 8 + np * 2 + nt];
                const int col = colBase + wn * 64 + np * 16 + nt * 8 + et;
                #pragma unroll
                for (int hf = 0; hf < 2; hf++) {
                    const long long r = rowBase + wm * 32 + mi * 16 + eg + hf * 8;
                    float2 o; o.x = cf[hf * 2]; o.y = cf[hf * 2 + 1];
                    *(float2*)(C + zC + r * (long long)N + col) = o;
                }
            }
}

// ---------------------------------------------------------------------------
// Output head (ODIM = 1)
// ---------------------------------------------------------------------------
__global__ __launch_bounds__(256) void out_kernel(
    const float* __restrict__ x, const float* __restrict__ ow,
    const float* __restrict__ ob, float* __restrict__ out)
{
    int warp = threadIdx.x >> 5, lane = threadIdx.x & 31;
    long long row = (long long)blockIdx.x * 8 + warp;
    const float* xr = x + row * cD;
    float s = 0.0f;
    #pragma unroll
    for (int j = lane; j < cD; j += 32) s += xr[j] * ow[j];
    #pragma unroll
    for (int o = 16; o; o >>= 1) s += __shfl_xor_sync(0xffffffffu, s, o);
    if (lane == 0) out[row] = s + ob[0];
}

// ---------------------------------------------------------------------------
// Launch
// ---------------------------------------------------------------------------
extern "C" void kernel_launch(void* const* d_in, const int* in_sizes, int n_in,
                              void* d_out, int out_size)
{
    (void)in_sizes; (void)n_in; (void)out_size;
    const float* z    = (const float*)d_in[0];
    const float* c    = (const float*)d_in[1];
    const float* encw = (const float*)d_in[2];
    const float* encb = (const float*)d_in[3];
    const float* beta = (const float*)d_in[4];
    const float* wq   = (const float*)d_in[5];
    const float* bq   = (const float*)d_in[6];
    const float* wk   = (const float*)d_in[7];
    const float* bk   = (const float*)d_in[8];
    const float* wv   = (const float*)d_in[9];
    const float* bv   = (const float*)d_in[10];
    const float* ln1w = (const float*)d_in[11];
    const float* ln1b = (const float*)d_in[12];
    const float* ln2w = (const float*)d_in[13];
    const float* ln2b = (const float*)d_in[14];
    const float* f1w  = (const float*)d_in[15];
    const float* f1b  = (const float*)d_in[16];
    const float* f2w  = (const float*)d_in[17];
    const float* f2b  = (const float*)d_in[18];
    const float* ow   = (const float*)d_in[19];
    const float* ob   = (const float*)d_in[20];

    float *x, *ao, *att, *tab;
    cudaGetSymbolAddress((void**)&x,   g_x);
    cudaGetSymbolAddress((void**)&ao,  g_ao);
    cudaGetSymbolAddress((void**)&att, g_att);
    cudaGetSymbolAddress((void**)&tab, g_tab);
    __nv_bfloat16 *vh, *vl, *ph, *pl;
    cudaGetSymbolAddress((void**)&vh, g_vh); cudaGetSymbolAddress((void**)&vl, g_vl);
    cudaGetSymbolAddress((void**)&ph, g_ph); cudaGetSymbolAddress((void**)&pl, g_pl);
    int8_t *xn1, *xn0, *q1, *q0, *k1, *k0, *h1, *h0;
    int8_t *wq1, *wq0, *wk1, *wk0, *wv1, *wv0, *f11, *f10, *f21, *f20;
    float *xns, *qs, *ks, *hs, *wqs, *wks, *wvs, *f1s, *f2s;
    cudaGetSymbolAddress((void**)&xn1, g_xn1); cudaGetSymbolAddress((void**)&xn0, g_xn0);
    cudaGetSymbolAddress((void**)&q1,  g_q1);  cudaGetSymbolAddress((void**)&q0,  g_q0);
    cudaGetSymbolAddress((void**)&k1,  g_k1);  cudaGetSymbolAddress((void**)&k0,  g_k0);
    cudaGetSymbolAddress((void**)&h1,  g_h1);  cudaGetSymbolAddress((void**)&h0,  g_h0);
    cudaGetSymbolAddress((void**)&wq1, g_wq1); cudaGetSymbolAddress((void**)&wq0, g_wq0);
    cudaGetSymbolAddress((void**)&wk1, g_wk1); cudaGetSymbolAddress((void**)&wk0, g_wk0);
    cudaGetSymbolAddress((void**)&wv1, g_wv1); cudaGetSymbolAddress((void**)&wv0, g_wv0);
    cudaGetSymbolAddress((void**)&f11, g_f11); cudaGetSymbolAddress((void**)&f10, g_f10);
    cudaGetSymbolAddress((void**)&f21, g_f21); cudaGetSymbolAddress((void**)&f20, g_f20);
    cudaGetSymbolAddress((void**)&xns, g_xns); cudaGetSymbolAddress((void**)&qs,  g_qs);
    cudaGetSymbolAddress((void**)&ks,  g_ks);  cudaGetSymbolAddress((void**)&hs,  g_hs);
    cudaGetSymbolAddress((void**)&wqs, g_wqs); cudaGetSymbolAddress((void**)&wks, g_wks);
    cudaGetSymbolAddress((void**)&wvs, g_wvs); cudaGetSymbolAddress((void**)&f1s, g_f1s);
    cudaGetSymbolAddress((void**)&f2s, g_f2s);

    cudaFuncSetAttribute(qgemm<true,  false, false, false>, cudaFuncAttributeMaxDynamicSharedMemorySize, Q_SMEM);
    cudaFuncSetAttribute(qgemm<false, true,  false, false>, cudaFuncAttributeMaxDynamicSharedMemorySize, Q_SMEM);
    cudaFuncSetAttribute(qgemm<true,  false, true,  false>, cudaFuncAttributeMaxDynamicSharedMemorySize, Q_SMEM);
    cudaFuncSetAttribute(qgemm<true,  false, false, true >, cudaFuncAttributeMaxDynamicSharedMemorySize, Q_SMEM);
    cudaFuncSetAttribute(tgemm_nn, cudaFuncAttributeMaxDynamicSharedMemorySize, T_SMEM);

    const long long SD  = (long long)cS * cD;
    const long long SSq = (long long)cS * cS;
    const float inv_sqrt_d = 0.044194173824159216f;
    float* kf = att;   // fp32 staging for K (g_att free until QK^T)
    float* qf = ao;    // fp32 staging for Q (g_ao free until PV)
    float* hf = att;   // fp32 staging for h (g_att free after softmax)

    enc_kernel<<<(cM * cD + 255) / 256, 256>>>(z, c, encw, encb, x);              // 0
    btab_all<<<(cL * cS + 255) / 256, 256>>>(beta, tab);                          // 1
    wquant_all<<<3 * cL * cD + cL * cF + cL * cD, 256>>>(                         // 2
        wq, wk, wv, f1w, f2w, wq1, wq0, wk1, wk0, wv1, wv0, f11, f10, f21, f20,
        wqs, wks, wvs, f1s, f2s);

    for (int l = 0; l < cL; l++) {
        const long long oQ = (long long)l * cD * cD;
        const long long oF1 = (long long)l * cF * cD;
        const long long oF2 = (long long)l * cD * cF;

        // xn = LN1(x) -> int8 limbs + row scales
        ln_q_kernel<<<cM, 128>>>(x, ln1w + l * cD, ln1b + l * cD, xn1, xn0, xns);

        dim3 gQKV(cD / 128, cM / 128, 1);
        // Q -> fp32 staging, K -> fp32 staging (launch 5 in first layer = K qgemm)
        qgemm<true, false, false, false><<<gQKV, 256, Q_SMEM>>>(
            xn1, xn0, wq1 + oQ, wq0 + oQ, xns, wqs + l * cD, bq + l * cD, (const float*)0,
            qf, (__nv_bfloat16*)0, (__nv_bfloat16*)0, cD, cD, 0, 0, 0, 0, 0, 1.0f);
        qgemm<true, false, false, false><<<gQKV, 256, Q_SMEM>>>(
            xn1, xn0, wk1 + oQ, wk0 + oQ, xns, wks + l * cD, bk + l * cD, (const float*)0,
            kf, (__nv_bfloat16*)0, (__nv_bfloat16*)0, cD, cD, 0, 0, 0, 0, 0, 1.0f);
        rowquant_kernel<<<cM, 256>>>(qf, q1, q0, qs, cD);
        rowquant_kernel<<<cM, 256>>>(kf, k1, k0, ks, cD);
        // V -> bf16 hi/lo directly
        qgemm<false, true, false, false><<<gQKV, 256, Q_SMEM>>>(
            xn1, xn0, wv1 + oQ, wv0 + oQ, xns, wvs + l * cD, bv + l * cD, (const float*)0,
            (float*)0, vh, vl, cD, cD, 0, 0, 0, 0, 0, 1.0f);

        // att = Q @ K^T / sqrt(d)   (int8, batched)
        dim3 gS(cS / 128, cS / 128, cB);
        qgemm<true, false, false, false><<<gS, 256, Q_SMEM>>>(
            q1, q0, k1, k0, qs, ks, (const float*)0, (const float*)0,
            att, (__nv_bfloat16*)0, (__nv_bfloat16*)0, cS, cD, SD, SD, SSq, cS, cS, inv_sqrt_d);

        softmax_kernel<<<dim3(cS, cB), 256>>>(att, tab + l * cS, ph, pl);

        // ao = P @ V   (bf16 3-term, NN)
        dim3 gV(cD / 128, cS / 128, cB);
        tgemm_nn<<<gV, 256, T_SMEM>>>(ph, pl, vh, vl, ao, cD, cS, SSq, SD, SD);

        // x = LN1(x + ao)
        ln_kernel<<<cM, 128>>>(x, ao, ln1w + l * cD, ln1b + l * cD, x);
        // xn2 = LN2(x) -> limbs
        ln_q_kernel<<<cM, 128>>>(x, ln2w + l * cD, ln2b + l * cD, xn1, xn0, xns);

        // h = relu(xn2 @ W1^T + b1) -> fp32 staging, then row quant
        dim3 g1(cF / 128, cM / 128, 1);
        qgemm<true, false, true, false><<<g1, 256, Q_SMEM>>>(
            xn1, xn0, f11 + oF1, f10 + oF1, xns, f1s + l * cF, f1b + l * cF, (const float*)0,
            hf, (__nv_bfloat16*)0, (__nv_bfloat16*)0, cF, cD, 0, 0, 0, 0, 0, 1.0f);
        rowquant_kernel<<<cM, 256>>>(hf, h1, h0, hs, cF);

        // x = x + h @ W2^T + b2
        dim3 g2(cD / 128, cM / 128, 1);
        qgemm<true, false, false, true><<<g2, 256, Q_SMEM>>>(
            h1, h0, f21 + oF2, f20 + oF2, hs, f2s + l * cD, f2b + l * cD, x,
            x, (__nv_bfloat16*)0, (__nv_bfloat16*)0, cD, cF, 0, 0, 0, 0, 0, 1.0f);
    }

    out_kernel<<<cM / 8, 256>>>(x, ow, ob, (float*)d_out);
}